// round 12
// baseline (speedup 1.0000x reference)
#include <cuda_runtime.h>
#include <cstdint>

typedef unsigned long long ull;

// Problem constants (fixed by setup_inputs)
#define N_SRC  100000
#define N_DST  20000
#define NE     600000
#define D      128
#define KDIM   256          // 2*D
#define OUT_F  128

// GEMM tile config
#define BM     48
#define ROWS_W 6
#define WPAD   128
#define ZPAD   50
#define SMEM_BYTES ((KDIM * ZPAD + KDIM * WPAD) * 4)   // 182272 B

#define NQ        (NE / 4)   // 150000 int4 quads
#define WT_BLOCKS 128        // 128*256 = 32768 = OUT_F*KDIM
#define AGG_ROWS  8          // rows per agg block (warp per row)
#define AGG_CACHE 1280       // smem index cache per block (avg need ~240)

// Scratch (allocation-free rule: __device__ globals; zero-initialized at load)
__device__ __align__(16) int g_count[N_DST];   // invariant: zero at entry (restored by agg)
__device__ __align__(16) int g_off[N_DST];
__device__ __align__(16) int g_cur[N_DST];
__device__ int   g_src_sorted[NE];
__device__ __align__(16) float g_nb[N_DST * D];
__device__ __align__(16) float g_Wt[KDIM * OUT_F];   // W transposed: g_Wt[k][o]

// ---- packed f32x2 helpers (Blackwell FFMA2) --------------------------------
__device__ __forceinline__ ull pack2(float a, float b) {
    ull r; asm("mov.b64 %0, {%1, %2};" : "=l"(r) : "f"(a), "f"(b)); return r;
}
__device__ __forceinline__ void unpack2(ull v, float& lo, float& hi) {
    asm("mov.b64 {%0, %1}, %2;" : "=f"(lo), "=f"(hi) : "l"(v));
}
__device__ __forceinline__ ull fma2(ull a, ull b, ull c) {
    ull d; asm("fma.rn.f32x2 %0, %1, %2, %3;" : "=l"(d) : "l"(a), "l"(b), "l"(c));
    return d;
}

// ---------------------------------------------------------------------------
// 1: prep = W-transpose (blocks [0,128)) + degree count (fire-and-forget RED).
// ---------------------------------------------------------------------------
__global__ void prep_kernel(const float* __restrict__ W,
                            const int4* __restrict__ edst4) {
    int b = blockIdx.x;
    if (b < WT_BLOCKS) {
        int i = b * 256 + threadIdx.x;       // 32768 elems exactly
        int o = i >> 8;
        int k = i & 255;
        g_Wt[k * OUT_F + o] = W[i];
        return;
    }
    int i = (b - WT_BLOCKS) * 256 + threadIdx.x;
    if (i < NQ) {
        int4 d = edst4[i];
        atomicAdd(&g_count[d.x], 1);   // return unused -> RED
        atomicAdd(&g_count[d.y], 1);
        atomicAdd(&g_count[d.z], 1);
        atomicAdd(&g_count[d.w], 1);
    }
}

// ---------------------------------------------------------------------------
// 2: exclusive scan of counts -> offsets (+cursors). Single block, 1024 thr.
//    Fully int4-vectorized I/O: thread t owns elements [t*20, t*20+20).
// ---------------------------------------------------------------------------
#define PER_T  20            // = 5 int4 per thread; 1000 active threads
#define PER_T4 5
__global__ void __launch_bounds__(1024, 1) scan_kernel() {
    __shared__ int warp_sums[32];
    const int tid  = threadIdx.x;
    const int lane = tid & 31;
    const int wrp  = tid >> 5;
    const bool active = (tid * PER_T < N_DST);   // tid < 1000

    int v[PER_T];
    if (active) {
        const int4* c4 = (const int4*)g_count;
#pragma unroll
        for (int q = 0; q < PER_T4; q++) {
            int4 x = c4[tid * PER_T4 + q];       // 5 independent LDG.128
            v[q * 4 + 0] = x.x; v[q * 4 + 1] = x.y;
            v[q * 4 + 2] = x.z; v[q * 4 + 3] = x.w;
        }
    } else {
#pragma unroll
        for (int j = 0; j < PER_T; j++) v[j] = 0;
    }

    // in-register exclusive prefix over the 20 values
    int total = 0;
#pragma unroll
    for (int j = 0; j < PER_T; j++) {
        int x = v[j];
        v[j] = total;
        total += x;
    }

    // warp inclusive scan of per-thread totals
    int inc = total;
#pragma unroll
    for (int d = 1; d < 32; d <<= 1) {
        int t = __shfl_up_sync(0xffffffffu, inc, d);
        if (lane >= d) inc += t;
    }
    if (lane == 31) warp_sums[wrp] = inc;
    __syncthreads();

    if (wrp == 0) {
        int w = warp_sums[lane];
        int winc = w;
#pragma unroll
        for (int d = 1; d < 32; d <<= 1) {
            int t = __shfl_up_sync(0xffffffffu, winc, d);
            if (lane >= d) winc += t;
        }
        warp_sums[lane] = winc - w;   // exclusive warp base
    }
    __syncthreads();

    if (active) {
        int base = warp_sums[wrp] + (inc - total);
        int4* o4 = (int4*)g_off;
        int4* u4 = (int4*)g_cur;
#pragma unroll
        for (int q = 0; q < PER_T4; q++) {
            int4 x;
            x.x = base + v[q * 4 + 0];
            x.y = base + v[q * 4 + 1];
            x.z = base + v[q * 4 + 2];
            x.w = base + v[q * 4 + 3];
            o4[tid * PER_T4 + q] = x;            // STG.128
            u4[tid * PER_T4 + q] = x;
        }
    }
}

// ---------------------------------------------------------------------------
// 3: bucket-fill src indices into CSR order (cursor atomics, 4 edges/thread)
// ---------------------------------------------------------------------------
__global__ void fill_kernel(const int4* __restrict__ esrc4,
                            const int4* __restrict__ edst4) {
    int i = blockIdx.x * blockDim.x + threadIdx.x;
    if (i < NQ) {
        int4 d = edst4[i];
        int4 s = esrc4[i];
        int p0 = atomicAdd(&g_cur[d.x], 1);
        int p1 = atomicAdd(&g_cur[d.y], 1);
        int p2 = atomicAdd(&g_cur[d.z], 1);
        int p3 = atomicAdd(&g_cur[d.w], 1);
        g_src_sorted[p0] = s.x;
        g_src_sorted[p1] = s.y;
        g_src_sorted[p2] = s.z;
        g_src_sorted[p3] = s.w;
    }
}

// ---------------------------------------------------------------------------
// 4: aggregation. Warp per row; block of 8 rows stages its contiguous CSR
//    index range in smem; fast path 8-wide unrolled (MLP=8).
//    Also restores g_count==0 for the next call.
// ---------------------------------------------------------------------------
__global__ void __launch_bounds__(256) agg_kernel(const float4* __restrict__ h4) {
    __shared__ int s_idx[AGG_CACHE];
    __shared__ int s_off[AGG_ROWS + 1];

    const int tid = threadIdx.x;
    const int row0 = blockIdx.x * AGG_ROWS;

    if (tid <= AGG_ROWS) {
        int r = row0 + tid;
        s_off[tid] = (r >= N_DST) ? NE : g_off[r];
    }
    if (tid < AGG_ROWS && row0 + tid < N_DST) g_count[row0 + tid] = 0;
    __syncthreads();

    const int ebase   = s_off[0];
    const int nbedges = s_off[AGG_ROWS] - ebase;
    for (int i = tid; i < nbedges && i < AGG_CACHE; i += 256)
        s_idx[i] = g_src_sorted[ebase + i];
    __syncthreads();

    const int wrp  = tid >> 5;
    const int lane = tid & 31;
    const int row  = row0 + wrp;
    if (row >= N_DST) return;

    const int start = s_off[wrp] - ebase;           // local offset
    const int cnt   = s_off[wrp + 1] - s_off[wrp];

    float4 a0 = make_float4(0.f, 0.f, 0.f, 0.f);
    float4 a1 = make_float4(0.f, 0.f, 0.f, 0.f);

    int j = 0;
    if (start + cnt <= AGG_CACHE) {
        // fast path: all indices cached; 8 independent gathers per iter
        for (; j + 8 <= cnt; j += 8) {
            int s0 = s_idx[start + j + 0];
            int s1 = s_idx[start + j + 1];
            int s2 = s_idx[start + j + 2];
            int s3 = s_idx[start + j + 3];
            int s4 = s_idx[start + j + 4];
            int s5 = s_idx[start + j + 5];
            int s6 = s_idx[start + j + 6];
            int s7 = s_idx[start + j + 7];
            float4 v0 = h4[s0 * (D / 4) + lane];
            float4 v1 = h4[s1 * (D / 4) + lane];
            float4 v2 = h4[s2 * (D / 4) + lane];
            float4 v3 = h4[s3 * (D / 4) + lane];
            float4 v4 = h4[s4 * (D / 4) + lane];
            float4 v5 = h4[s5 * (D / 4) + lane];
            float4 v6 = h4[s6 * (D / 4) + lane];
            float4 v7 = h4[s7 * (D / 4) + lane];
            a0.x += (v0.x + v1.x) + (v2.x + v3.x);
            a0.y += (v0.y + v1.y) + (v2.y + v3.y);
            a0.z += (v0.z + v1.z) + (v2.z + v3.z);
            a0.w += (v0.w + v1.w) + (v2.w + v3.w);
            a1.x += (v4.x + v5.x) + (v6.x + v7.x);
            a1.y += (v4.y + v5.y) + (v6.y + v7.y);
            a1.z += (v4.z + v5.z) + (v6.z + v7.z);
            a1.w += (v4.w + v5.w) + (v6.w + v7.w);
        }
        for (; j < cnt; j++) {
            int s = s_idx[start + j];
            float4 v = h4[s * (D / 4) + lane];
            a0.x += v.x; a0.y += v.y; a0.z += v.z; a0.w += v.w;
        }
    } else {
        // overflow path (block has >AGG_CACHE edges): read indices from global
        for (; j < cnt; j++) {
            int li = start + j;
            int s = (li < AGG_CACHE) ? s_idx[li] : g_src_sorted[ebase + li];
            float4 v = h4[s * (D / 4) + lane];
            a0.x += v.x; a0.y += v.y; a0.z += v.z; a0.w += v.w;
        }
    }

    float inv = 1.0f / fmaxf((float)cnt, 1.0f);
    float4 acc;
    acc.x = (a0.x + a1.x) * inv;
    acc.y = (a0.y + a1.y) * inv;
    acc.z = (a0.z + a1.z) * inv;
    acc.w = (a0.w + a1.w) * inv;
    ((float4*)g_nb)[row * (D / 4) + lane] = acc;
}

// ---------------------------------------------------------------------------
// 5: out = relu( [h[:N_DST] | h_neigh] @ W^T + b )  via packed FFMA2
// ---------------------------------------------------------------------------
__global__ void __launch_bounds__(256, 1)
gemm_kernel(const float* __restrict__ h,
            const float* __restrict__ bias,
            float* __restrict__ out) {
    extern __shared__ float smem[];
    float* zsT = smem;                  // [KDIM][ZPAD]
    float* ws  = smem + KDIM * ZPAD;    // [KDIM][WPAD]

    const int t  = threadIdx.x;
    const int r0 = blockIdx.x * BM;

    {
        const float4* src = (const float4*)g_Wt;
        float4*       dst = (float4*)ws;
        for (int i = t; i < KDIM * OUT_F / 4; i += 256) dst[i] = src[i];
    }

    for (int i = t; i < BM * (KDIM / 4); i += 256) {
        int r  = i >> 6;
        int k4 = i & 63;
        int rg = r0 + r;
        int rc = rg < N_DST ? rg : (N_DST - 1);
        float4 v = (k4 < 32) ? ((const float4*)h)[rc * 32 + k4]
                             : ((const float4*)g_nb)[rc * 32 + (k4 - 32)];
        int k = k4 * 4;
        zsT[(k + 0) * ZPAD + r] = v.x;
        zsT[(k + 1) * ZPAD + r] = v.y;
        zsT[(k + 2) * ZPAD + r] = v.z;
        zsT[(k + 3) * ZPAD + r] = v.w;
    }
    __syncthreads();

    const int lane = t & 31;
    const int wrp  = t >> 5;

    ull acc[3][4];
#pragma unroll
    for (int p = 0; p < 3; p++)
#pragma unroll
        for (int jj = 0; jj < 4; jj++) acc[p][jj] = 0ULL;

    const float* zcol = zsT + wrp * ROWS_W;
    const float* wrow = ws + lane * 4;

#pragma unroll 8
    for (int k = 0; k < KDIM; k++) {
        float4 w4 = *(const float4*)&wrow[k * WPAD];
        ull w0 = pack2(w4.x, w4.x);
        ull w1 = pack2(w4.y, w4.y);
        ull w2 = pack2(w4.z, w4.z);
        ull w3 = pack2(w4.w, w4.w);
        const float* z = zcol + k * ZPAD;
        ull z0 = *(const ull*)&z[0];
        ull z1 = *(const ull*)&z[2];
        ull z2 = *(const ull*)&z[4];
        acc[0][0] = fma2(z0, w0, acc[0][0]);
        acc[0][1] = fma2(z0, w1, acc[0][1]);
        acc[0][2] = fma2(z0, w2, acc[0][2]);
        acc[0][3] = fma2(z0, w3, acc[0][3]);
        acc[1][0] = fma2(z1, w0, acc[1][0]);
        acc[1][1] = fma2(z1, w1, acc[1][1]);
        acc[1][2] = fma2(z1, w2, acc[1][2]);
        acc[1][3] = fma2(z1, w3, acc[1][3]);
        acc[2][0] = fma2(z2, w0, acc[2][0]);
        acc[2][1] = fma2(z2, w1, acc[2][1]);
        acc[2][2] = fma2(z2, w2, acc[2][2]);
        acc[2][3] = fma2(z2, w3, acc[2][3]);
    }

    float4 bv = *(const float4*)&bias[lane * 4];

#pragma unroll
    for (int p = 0; p < 3; p++) {
        float lo0, hi0, lo1, hi1, lo2, hi2, lo3, hi3;
        unpack2(acc[p][0], lo0, hi0);
        unpack2(acc[p][1], lo1, hi1);
        unpack2(acc[p][2], lo2, hi2);
        unpack2(acc[p][3], lo3, hi3);
        int rg = r0 + wrp * ROWS_W + 2 * p;
        if (rg < N_DST) {
            float4 res;
            res.x = fmaxf(lo0 + bv.x, 0.0f);
            res.y = fmaxf(lo1 + bv.y, 0.0f);
            res.z = fmaxf(lo2 + bv.z, 0.0f);
            res.w = fmaxf(lo3 + bv.w, 0.0f);
            *(float4*)&out[rg * OUT_F + lane * 4] = res;
        }
        if (rg + 1 < N_DST) {
            float4 res;
            res.x = fmaxf(hi0 + bv.x, 0.0f);
            res.y = fmaxf(hi1 + bv.y, 0.0f);
            res.z = fmaxf(hi2 + bv.z, 0.0f);
            res.w = fmaxf(hi3 + bv.w, 0.0f);
            *(float4*)&out[(rg + 1) * OUT_F + lane * 4] = res;
        }
    }
}

// ---------------------------------------------------------------------------
extern "C" void kernel_launch(void* const* d_in, const int* in_sizes, int n_in,
                              void* d_out, int out_size) {
    const float* h    = (const float*)d_in[0];
    const int*   esrc = (const int*)d_in[1];    // int32: JAX x64 disabled
    const int*   edst = (const int*)d_in[2];    // int32
    const float* W    = (const float*)d_in[3];
    const float* bias = (const float*)d_in[4];
    float*       out  = (float*)d_out;

    cudaFuncSetAttribute(gemm_kernel,
                         cudaFuncAttributeMaxDynamicSharedMemorySize, SMEM_BYTES);

    int count_blocks = (NQ + 255) / 256;                 // 586
    prep_kernel<<<WT_BLOCKS + count_blocks, 256>>>(W, (const int4*)edst);
    scan_kernel<<<1, 1024>>>();
    fill_kernel<<<count_blocks, 256>>>((const int4*)esrc, (const int4*)edst);
    agg_kernel<<<N_DST / AGG_ROWS, 256>>>((const float4*)h);
    gemm_kernel<<<(N_DST + BM - 1) / BM, 256, SMEM_BYTES>>>(h, bias, out);
}

// round 13
// speedup vs baseline: 1.3517x; 1.3517x over previous
#include <cuda_runtime.h>
#include <cstdint>

typedef unsigned long long ull;

// Problem constants (fixed by setup_inputs)
#define N_SRC  100000
#define N_DST  20000
#define NE     600000
#define D      128
#define KDIM   256          // 2*D
#define OUT_F  128

// GEMM tile config
#define BM     48
#define ROWS_W 6
#define WPAD   128
#define ZPAD   50
#define SMEM_BYTES ((KDIM * ZPAD + KDIM * WPAD) * 4)   // 182272 B

#define NQ        (NE / 4)   // 150000 int4 quads
#define WT_BLOCKS 128        // 128*256 = 32768 = OUT_F*KDIM
#define AGG_ROWS  8          // rows per agg block (warp per row)
#define AGG_CACHE 1280       // smem index cache per block (avg need ~240)

// Scratch (allocation-free rule: __device__ globals; zero-initialized at load)
__device__ __align__(16) int g_count[N_DST];   // invariant: zero at entry (restored by agg)
__device__ __align__(16) int g_off[N_DST];
__device__ __align__(16) int g_cur[N_DST];
__device__ int   g_src_sorted[NE];
__device__ __align__(16) float g_nb[N_DST * D];
__device__ __align__(16) float g_Wt[KDIM * OUT_F];   // W transposed: g_Wt[k][o]

// ---- packed f32x2 helpers (Blackwell FFMA2) --------------------------------
__device__ __forceinline__ ull pack2(float a, float b) {
    ull r; asm("mov.b64 %0, {%1, %2};" : "=l"(r) : "f"(a), "f"(b)); return r;
}
__device__ __forceinline__ void unpack2(ull v, float& lo, float& hi) {
    asm("mov.b64 {%0, %1}, %2;" : "=f"(lo), "=f"(hi) : "l"(v));
}
__device__ __forceinline__ ull fma2(ull a, ull b, ull c) {
    ull d; asm("fma.rn.f32x2 %0, %1, %2, %3;" : "=l"(d) : "l"(a), "l"(b), "l"(c));
    return d;
}

// ---------------------------------------------------------------------------
// 1: prep = W-transpose (blocks [0,128)) + degree count (fire-and-forget RED).
// ---------------------------------------------------------------------------
__global__ void prep_kernel(const float* __restrict__ W,
                            const int4* __restrict__ edst4) {
    int b = blockIdx.x;
    if (b < WT_BLOCKS) {
        int i = b * 256 + threadIdx.x;       // 32768 elems exactly
        int o = i >> 8;
        int k = i & 255;
        g_Wt[k * OUT_F + o] = W[i];
        return;
    }
    int i = (b - WT_BLOCKS) * 256 + threadIdx.x;
    if (i < NQ) {
        int4 d = edst4[i];
        atomicAdd(&g_count[d.x], 1);   // return unused -> RED
        atomicAdd(&g_count[d.y], 1);
        atomicAdd(&g_count[d.z], 1);
        atomicAdd(&g_count[d.w], 1);
    }
}

// ---------------------------------------------------------------------------
// 2: exclusive scan of counts -> offsets (+cursors). Single block, 1024 thr.
//    Fully int4-vectorized I/O: thread t owns elements [t*20, t*20+20).
// ---------------------------------------------------------------------------
#define PER_T  20            // = 5 int4 per thread; 1000 active threads
#define PER_T4 5
__global__ void __launch_bounds__(1024, 1) scan_kernel() {
    __shared__ int warp_sums[32];
    const int tid  = threadIdx.x;
    const int lane = tid & 31;
    const int wrp  = tid >> 5;
    const bool active = (tid * PER_T < N_DST);   // tid < 1000

    int v[PER_T];
    if (active) {
        const int4* c4 = (const int4*)g_count;
#pragma unroll
        for (int q = 0; q < PER_T4; q++) {
            int4 x = c4[tid * PER_T4 + q];       // 5 independent LDG.128
            v[q * 4 + 0] = x.x; v[q * 4 + 1] = x.y;
            v[q * 4 + 2] = x.z; v[q * 4 + 3] = x.w;
        }
    } else {
#pragma unroll
        for (int j = 0; j < PER_T; j++) v[j] = 0;
    }

    // in-register exclusive prefix over the 20 values
    int total = 0;
#pragma unroll
    for (int j = 0; j < PER_T; j++) {
        int x = v[j];
        v[j] = total;
        total += x;
    }

    // warp inclusive scan of per-thread totals
    int inc = total;
#pragma unroll
    for (int d = 1; d < 32; d <<= 1) {
        int t = __shfl_up_sync(0xffffffffu, inc, d);
        if (lane >= d) inc += t;
    }
    if (lane == 31) warp_sums[wrp] = inc;
    __syncthreads();

    if (wrp == 0) {
        int w = warp_sums[lane];
        int winc = w;
#pragma unroll
        for (int d = 1; d < 32; d <<= 1) {
            int t = __shfl_up_sync(0xffffffffu, winc, d);
            if (lane >= d) winc += t;
        }
        warp_sums[lane] = winc - w;   // exclusive warp base
    }
    __syncthreads();

    if (active) {
        int base = warp_sums[wrp] + (inc - total);
        int4* o4 = (int4*)g_off;
        int4* u4 = (int4*)g_cur;
#pragma unroll
        for (int q = 0; q < PER_T4; q++) {
            int4 x;
            x.x = base + v[q * 4 + 0];
            x.y = base + v[q * 4 + 1];
            x.z = base + v[q * 4 + 2];
            x.w = base + v[q * 4 + 3];
            o4[tid * PER_T4 + q] = x;            // STG.128
            u4[tid * PER_T4 + q] = x;
        }
    }
}

// ---------------------------------------------------------------------------
// 3: bucket-fill src indices into CSR order (cursor atomics, 4 edges/thread)
// ---------------------------------------------------------------------------
__global__ void fill_kernel(const int4* __restrict__ esrc4,
                            const int4* __restrict__ edst4) {
    int i = blockIdx.x * blockDim.x + threadIdx.x;
    if (i < NQ) {
        int4 d = edst4[i];
        int4 s = esrc4[i];
        int p0 = atomicAdd(&g_cur[d.x], 1);
        int p1 = atomicAdd(&g_cur[d.y], 1);
        int p2 = atomicAdd(&g_cur[d.z], 1);
        int p3 = atomicAdd(&g_cur[d.w], 1);
        g_src_sorted[p0] = s.x;
        g_src_sorted[p1] = s.y;
        g_src_sorted[p2] = s.z;
        g_src_sorted[p3] = s.w;
    }
}

// ---------------------------------------------------------------------------
// 4: aggregation. Warp per row; block of 8 rows stages its contiguous CSR
//    index range in smem (coalesced); 4-wide unroll (regs 32, occ ~84%).
//    Also restores g_count==0 for the next call.
// ---------------------------------------------------------------------------
__global__ void __launch_bounds__(256) agg_kernel(const float4* __restrict__ h4) {
    __shared__ int s_idx[AGG_CACHE];
    __shared__ int s_off[AGG_ROWS + 1];

    const int tid = threadIdx.x;
    const int row0 = blockIdx.x * AGG_ROWS;

    if (tid <= AGG_ROWS) {
        int r = row0 + tid;
        s_off[tid] = (r >= N_DST) ? NE : g_off[r];
    }
    if (tid < AGG_ROWS && row0 + tid < N_DST) g_count[row0 + tid] = 0;
    __syncthreads();

    const int ebase   = s_off[0];
    const int nbedges = s_off[AGG_ROWS] - ebase;
    for (int i = tid; i < nbedges && i < AGG_CACHE; i += 256)
        s_idx[i] = g_src_sorted[ebase + i];
    __syncthreads();

    const int wrp  = tid >> 5;
    const int lane = tid & 31;
    const int row  = row0 + wrp;
    if (row >= N_DST) return;

    const int start = s_off[wrp] - ebase;           // local offset
    const int cnt   = s_off[wrp + 1] - s_off[wrp];

    float4 a0 = make_float4(0.f, 0.f, 0.f, 0.f);
    float4 a1 = make_float4(0.f, 0.f, 0.f, 0.f);

    int j = 0;
    if (start + cnt <= AGG_CACHE) {
        // fast path: all indices cached
        for (; j + 4 <= cnt; j += 4) {
            int s0 = s_idx[start + j + 0];
            int s1 = s_idx[start + j + 1];
            int s2 = s_idx[start + j + 2];
            int s3 = s_idx[start + j + 3];
            float4 v0 = h4[s0 * (D / 4) + lane];
            float4 v1 = h4[s1 * (D / 4) + lane];
            float4 v2 = h4[s2 * (D / 4) + lane];
            float4 v3 = h4[s3 * (D / 4) + lane];
            a0.x += v0.x + v1.x; a0.y += v0.y + v1.y;
            a0.z += v0.z + v1.z; a0.w += v0.w + v1.w;
            a1.x += v2.x + v3.x; a1.y += v2.y + v3.y;
            a1.z += v2.z + v3.z; a1.w += v2.w + v3.w;
        }
        for (; j < cnt; j++) {
            int s = s_idx[start + j];
            float4 v = h4[s * (D / 4) + lane];
            a0.x += v.x; a0.y += v.y; a0.z += v.z; a0.w += v.w;
        }
    } else {
        // overflow path (block has >AGG_CACHE edges): read indices from global
        for (; j < cnt; j++) {
            int li = start + j;
            int s = (li < AGG_CACHE) ? s_idx[li] : g_src_sorted[ebase + li];
            float4 v = h4[s * (D / 4) + lane];
            a0.x += v.x; a0.y += v.y; a0.z += v.z; a0.w += v.w;
        }
    }

    float inv = 1.0f / fmaxf((float)cnt, 1.0f);
    float4 acc;
    acc.x = (a0.x + a1.x) * inv;
    acc.y = (a0.y + a1.y) * inv;
    acc.z = (a0.z + a1.z) * inv;
    acc.w = (a0.w + a1.w) * inv;
    ((float4*)g_nb)[row * (D / 4) + lane] = acc;
}

// ---------------------------------------------------------------------------
// 5: out = relu( [h[:N_DST] | h_neigh] @ W^T + b )  via packed FFMA2
// ---------------------------------------------------------------------------
__global__ void __launch_bounds__(256, 1)
gemm_kernel(const float* __restrict__ h,
            const float* __restrict__ bias,
            float* __restrict__ out) {
    extern __shared__ float smem[];
    float* zsT = smem;                  // [KDIM][ZPAD]
    float* ws  = smem + KDIM * ZPAD;    // [KDIM][WPAD]

    const int t  = threadIdx.x;
    const int r0 = blockIdx.x * BM;

    {
        const float4* src = (const float4*)g_Wt;
        float4*       dst = (float4*)ws;
        for (int i = t; i < KDIM * OUT_F / 4; i += 256) dst[i] = src[i];
    }

    for (int i = t; i < BM * (KDIM / 4); i += 256) {
        int r  = i >> 6;
        int k4 = i & 63;
        int rg = r0 + r;
        int rc = rg < N_DST ? rg : (N_DST - 1);
        float4 v = (k4 < 32) ? ((const float4*)h)[rc * 32 + k4]
                             : ((const float4*)g_nb)[rc * 32 + (k4 - 32)];
        int k = k4 * 4;
        zsT[(k + 0) * ZPAD + r] = v.x;
        zsT[(k + 1) * ZPAD + r] = v.y;
        zsT[(k + 2) * ZPAD + r] = v.z;
        zsT[(k + 3) * ZPAD + r] = v.w;
    }
    __syncthreads();

    const int lane = t & 31;
    const int wrp  = t >> 5;

    ull acc[3][4];
#pragma unroll
    for (int p = 0; p < 3; p++)
#pragma unroll
        for (int jj = 0; jj < 4; jj++) acc[p][jj] = 0ULL;

    const float* zcol = zsT + wrp * ROWS_W;
    const float* wrow = ws + lane * 4;

#pragma unroll 8
    for (int k = 0; k < KDIM; k++) {
        float4 w4 = *(const float4*)&wrow[k * WPAD];
        ull w0 = pack2(w4.x, w4.x);
        ull w1 = pack2(w4.y, w4.y);
        ull w2 = pack2(w4.z, w4.z);
        ull w3 = pack2(w4.w, w4.w);
        const float* z = zcol + k * ZPAD;
        ull z0 = *(const ull*)&z[0];
        ull z1 = *(const ull*)&z[2];
        ull z2 = *(const ull*)&z[4];
        acc[0][0] = fma2(z0, w0, acc[0][0]);
        acc[0][1] = fma2(z0, w1, acc[0][1]);
        acc[0][2] = fma2(z0, w2, acc[0][2]);
        acc[0][3] = fma2(z0, w3, acc[0][3]);
        acc[1][0] = fma2(z1, w0, acc[1][0]);
        acc[1][1] = fma2(z1, w1, acc[1][1]);
        acc[1][2] = fma2(z1, w2, acc[1][2]);
        acc[1][3] = fma2(z1, w3, acc[1][3]);
        acc[2][0] = fma2(z2, w0, acc[2][0]);
        acc[2][1] = fma2(z2, w1, acc[2][1]);
        acc[2][2] = fma2(z2, w2, acc[2][2]);
        acc[2][3] = fma2(z2, w3, acc[2][3]);
    }

    float4 bv = *(const float4*)&bias[lane * 4];

#pragma unroll
    for (int p = 0; p < 3; p++) {
        float lo0, hi0, lo1, hi1, lo2, hi2, lo3, hi3;
        unpack2(acc[p][0], lo0, hi0);
        unpack2(acc[p][1], lo1, hi1);
        unpack2(acc[p][2], lo2, hi2);
        unpack2(acc[p][3], lo3, hi3);
        int rg = r0 + wrp * ROWS_W + 2 * p;
        if (rg < N_DST) {
            float4 res;
            res.x = fmaxf(lo0 + bv.x, 0.0f);
            res.y = fmaxf(lo1 + bv.y, 0.0f);
            res.z = fmaxf(lo2 + bv.z, 0.0f);
            res.w = fmaxf(lo3 + bv.w, 0.0f);
            *(float4*)&out[rg * OUT_F + lane * 4] = res;
        }
        if (rg + 1 < N_DST) {
            float4 res;
            res.x = fmaxf(hi0 + bv.x, 0.0f);
            res.y = fmaxf(hi1 + bv.y, 0.0f);
            res.z = fmaxf(hi2 + bv.z, 0.0f);
            res.w = fmaxf(hi3 + bv.w, 0.0f);
            *(float4*)&out[(rg + 1) * OUT_F + lane * 4] = res;
        }
    }
}

// ---------------------------------------------------------------------------
extern "C" void kernel_launch(void* const* d_in, const int* in_sizes, int n_in,
                              void* d_out, int out_size) {
    const float* h    = (const float*)d_in[0];
    const int*   esrc = (const int*)d_in[1];    // int32: JAX x64 disabled
    const int*   edst = (const int*)d_in[2];    // int32
    const float* W    = (const float*)d_in[3];
    const float* bias = (const float*)d_in[4];
    float*       out  = (float*)d_out;

    cudaFuncSetAttribute(gemm_kernel,
                         cudaFuncAttributeMaxDynamicSharedMemorySize, SMEM_BYTES);

    int count_blocks = (NQ + 255) / 256;                 // 586
    prep_kernel<<<WT_BLOCKS + count_blocks, 256>>>(W, (const int4*)edst);
    scan_kernel<<<1, 1024>>>();
    fill_kernel<<<count_blocks, 256>>>((const int4*)esrc, (const int4*)edst);
    agg_kernel<<<N_DST / AGG_ROWS, 256>>>((const float4*)h);
    gemm_kernel<<<(N_DST + BM - 1) / BM, 256, SMEM_BYTES>>>(h, bias, out);
}